// round 16
// baseline (speedup 1.0000x reference)
#include <cuda_runtime.h>
#include <cuda_fp16.h>
#include <cstdint>
#include <cstddef>

#define SEQ 2048
#define NHEADS 32

// ---------------- device scratch (fp16 planes) ----------------
__device__ __half g_xh[SEQ * 4096];
__device__ __half g_wqh[4096 * 4096], g_wql[4096 * 4096];
__device__ __half g_wkvh[4096 * 2048], g_wkvl[4096 * 2048];
__device__ __half g_woh[4096 * 4096], g_wol[4096 * 4096];
__device__ __half g_qh[SEQ * 4096];
__device__ __half g_kvh[SEQ * 2048];
__device__ __half g_ohh[SEQ * 4096];

#define MMAH16816(C, A0, A1, A2, A3, B0, B1)                                        \
    asm volatile(                                                                   \
        "mma.sync.aligned.m16n8k16.row.col.f32.f16.f16.f32 "                        \
        "{%0,%1,%2,%3},{%4,%5,%6,%7},{%8,%9},{%0,%1,%2,%3};"                        \
        : "+f"((C)[0]), "+f"((C)[1]), "+f"((C)[2]), "+f"((C)[3])                    \
        : "r"(A0), "r"(A1), "r"(A2), "r"(A3), "r"(B0), "r"(B1))
#define LDSM4(R0, R1, R2, R3, ADDR)                                                 \
    asm volatile("ldmatrix.sync.aligned.m8n8.x4.shared.b16 {%0,%1,%2,%3},[%4];"     \
                 : "=r"(R0), "=r"(R1), "=r"(R2), "=r"(R3) : "r"(ADDR))
#define LDSM4T(R0, R1, R2, R3, ADDR)                                                \
    asm volatile("ldmatrix.sync.aligned.m8n8.x4.trans.shared.b16 {%0,%1,%2,%3},[%4];" \
                 : "=r"(R0), "=r"(R1), "=r"(R2), "=r"(R3) : "r"(ADDR))
#define STS32(ADDR, V0) asm volatile("st.shared.b32 [%0],%1;" :: "r"(ADDR), "r"(V0))
#define CP16(saddr, gptr)                                                           \
    asm volatile("cp.async.cg.shared.global [%0], [%1], 16;" :: "r"(saddr), "l"(gptr))
#define CP_COMMIT() asm volatile("cp.async.commit_group;" ::: "memory")

// ---------------- prep kernels (one-time conversion) ----------------
__global__ void cvt_x(const float* __restrict__ in, __half* __restrict__ out, int n4) {
    int i = blockIdx.x * blockDim.x + threadIdx.x;
    if (i >= n4) return;
    float4 f = ((const float4*)in)[i];
    __half2 a = __floats2half2_rn(f.x, f.y);
    __half2 b = __floats2half2_rn(f.z, f.w);
    __half2* o = (__half2*)(out + (size_t)i * 4);
    o[0] = a; o[1] = b;
}

// w fp32 [4096][N] -> fp16 hi/lo planes [4096][ldo] at column offset co
__global__ void splitw(const float* __restrict__ w, int N4,
                       __half* __restrict__ wh, __half* __restrict__ wl,
                       int ldo, int co) {
    int i = blockIdx.x * blockDim.x + threadIdx.x;
    if (i >= 4096 * N4) return;
    int row = i / N4, c4 = i - row * N4;
    float4 f = ((const float4*)w)[i];
    __half2 h0 = __floats2half2_rn(f.x, f.y);
    __half2 h1 = __floats2half2_rn(f.z, f.w);
    float2 h0f = __half22float2(h0), h1f = __half22float2(h1);
    __half2 l0 = __floats2half2_rn(f.x - h0f.x, f.y - h0f.y);
    __half2 l1 = __floats2half2_rn(f.z - h1f.x, f.w - h1f.y);
    size_t off = (size_t)row * ldo + co + c4 * 4;
    ((__half2*)(wh + off))[0] = h0; ((__half2*)(wh + off))[1] = h1;
    ((__half2*)(wl + off))[0] = l0; ((__half2*)(wl + off))[1] = l1;
}

// ======================================================================
// preconverted fp16x2 GEMM: C[2048 x N] = A16 * (Bh + Bl).
// BM=128, BN=256, BK=64, 256 thr, warps 2(M)x4(N), warp tile 64x64.
// Pure cp.async mainloop, 2-deep, 64 stages.
// smem/stage: A 0..18432 (pitch 144) | Bh 18432..52224 (pitch 528) | Bl ..86016
#define W_STG 86016
#define W_BH  18432u
#define W_BL  52224u

template <bool OUTH>
__global__ void __launch_bounds__(256, 1) gemm_pc(
    const __half* __restrict__ A, int lda,
    const __half* __restrict__ Bh, const __half* __restrict__ Bl, int ldb,
    void* __restrict__ Cout, int ldc, int ropeLim,
    const float* __restrict__ cosp, const float* __restrict__ sinp)
{
    extern __shared__ char sh[];
    const int tid = threadIdx.x;
    const int lane = tid & 31, warp = tid >> 5;
    const int g = lane >> 2, t4 = lane & 3;
    const int wm = (warp & 1) * 64, wn = (warp >> 1) * 64;
    const int bm = blockIdx.y * 128, bn = blockIdx.x * 256;

    uint32_t sbase;
    asm("{ .reg .u64 t; cvta.to.shared.u64 t, %1; cvt.u32.u64 %0, t; }"
        : "=r"(sbase) : "l"(sh));

    // cp.async coords: A 4 chunks/thread, B 8+8 chunks/thread
    uint32_t aDst[4];
    const __half* aSrc[4];
#pragma unroll
    for (int j = 0; j < 4; j++) {
        int idx = tid + j * 256;
        int r = idx >> 3, c = idx & 7;
        aDst[j] = (uint32_t)(r * 144 + c * 16);
        aSrc[j] = A + (size_t)(bm + r) * lda + c * 8;
    }
    uint32_t bDst[8];
    const __half* bSrcH[8];
    const __half* bSrcL[8];
#pragma unroll
    for (int j = 0; j < 8; j++) {
        int idx = tid + j * 256;
        int kr = idx >> 5, c = idx & 31;
        bDst[j] = W_BH + (uint32_t)(kr * 528 + c * 16);
        bSrcH[j] = Bh + (size_t)kr * ldb + bn + c * 8;
        bSrcL[j] = Bl + (size_t)kr * ldb + bn + c * 8;
    }

    auto loadStage = [&](int t) {
        const uint32_t so = sbase + (uint32_t)(t & 1) * W_STG;
        const size_t ko = (size_t)t * 64;
#pragma unroll
        for (int j = 0; j < 4; j++) CP16(so + aDst[j], aSrc[j] + ko);
#pragma unroll
        for (int j = 0; j < 8; j++) {
            CP16(so + bDst[j], bSrcH[j] + ko * ldb);
            CP16(so + bDst[j] + (W_BL - W_BH), bSrcL[j] + ko * ldb);
        }
        CP_COMMIT();
    };

    const int lr = (lane & 7) + ((lane >> 3) & 1) * 8;
    const int lk = lane >> 4;
    uint32_t aAddr[4], bAddr[4];
#pragma unroll
    for (int mi = 0; mi < 4; mi++)
        aAddr[mi] = sbase + (uint32_t)((wm + mi * 16 + lr) * 144 + lk * 16);
#pragma unroll
    for (int nb = 0; nb < 4; nb++) {
        int kk = (lane & 7) + lk * 8;
        int nc = (wn >> 3) + nb * 2 + ((lane >> 3) & 1);
        bAddr[nb] = sbase + W_BH + (uint32_t)(kk * 528 + nc * 16);
    }

    float acc[4][8][4];
#pragma unroll
    for (int i = 0; i < 4; i++)
#pragma unroll
        for (int j = 0; j < 8; j++)
#pragma unroll
            for (int l = 0; l < 4; l++) acc[i][j][l] = 0.f;

    const int nK = 64;  // K = 4096, BK = 64
    loadStage(0);

    for (int t = 0; t < nK; t++) {
        asm volatile("cp.async.wait_group 0;" ::: "memory");
        __syncthreads();
        if (t + 1 < nK) loadStage(t + 1);
        const uint32_t so = (uint32_t)(t & 1) * W_STG;
#pragma unroll
        for (int kb = 0; kb < 4; kb++) {
            uint32_t AH[4][4], BH[8][2], BL[8][2];
#pragma unroll
            for (int mi = 0; mi < 4; mi++)
                LDSM4(AH[mi][0], AH[mi][1], AH[mi][2], AH[mi][3],
                      aAddr[mi] + so + kb * 32);
#pragma unroll
            for (int nb = 0; nb < 4; nb++) {
                uint32_t q0, q1, q2, q3;
                uint32_t bd = bAddr[nb] + so + kb * (16 * 528);
                LDSM4T(q0, q1, q2, q3, bd);
                BH[2 * nb][0] = q0; BH[2 * nb][1] = q2;
                BH[2 * nb + 1][0] = q1; BH[2 * nb + 1][1] = q3;
                LDSM4T(q0, q1, q2, q3, bd + (W_BL - W_BH));
                BL[2 * nb][0] = q0; BL[2 * nb][1] = q2;
                BL[2 * nb + 1][0] = q1; BL[2 * nb + 1][1] = q3;
            }
#pragma unroll
            for (int mi = 0; mi < 4; mi++)
#pragma unroll
                for (int ni = 0; ni < 8; ni++) {
                    MMAH16816(acc[mi][ni], AH[mi][0], AH[mi][1], AH[mi][2], AH[mi][3],
                              BL[ni][0], BL[ni][1]);
                    MMAH16816(acc[mi][ni], AH[mi][0], AH[mi][1], AH[mi][2], AH[mi][3],
                              BH[ni][0], BH[ni][1]);
                }
        }
    }

#pragma unroll
    for (int mi = 0; mi < 4; mi++) {
        int rowg = bm + wm + mi * 16 + g;
#pragma unroll
        for (int ni = 0; ni < 8; ni++) {
            int colg = bn + wn + ni * 8 + 2 * t4;
            float c0 = acc[mi][ni][0], c1 = acc[mi][ni][1];
            float c2 = acc[mi][ni][2], c3 = acc[mi][ni][3];
            if (colg < ropeLim) {
                int i = (colg & 127) >> 1;
                float cs = cosp[rowg * 64 + i], sn = sinp[rowg * 64 + i];
                float cs2 = cosp[(rowg + 8) * 64 + i], sn2 = sinp[(rowg + 8) * 64 + i];
                float o0 = c0 * cs - c1 * sn, o1 = c0 * sn + c1 * cs;
                float o2 = c2 * cs2 - c3 * sn2, o3 = c2 * sn2 + c3 * cs2;
                c0 = o0; c1 = o1; c2 = o2; c3 = o3;
            }
            if (OUTH) {
                __half* Ch = (__half*)Cout;
                *(__half2*)(Ch + (size_t)rowg * ldc + colg) = __floats2half2_rn(c0, c1);
                *(__half2*)(Ch + (size_t)(rowg + 8) * ldc + colg) = __floats2half2_rn(c2, c3);
            } else {
                float* Cf = (float*)Cout;
                *(float2*)(Cf + (size_t)rowg * ldc + colg) = make_float2(c0, c1);
                *(float2*)(Cf + (size_t)(rowg + 8) * ldc + colg) = make_float2(c2, c3);
            }
        }
    }
}

// ======== flash attention (K/V from merged [2048][2048] buffer; O -> fp16) ====
#define FK_K   34816u
#define FK_V   104448u
#define FK_P   139264u
#define FK_RED 174080u
#define FK_SM  178176

__global__ void __launch_bounds__(512, 1) flash_k(
    const __half* __restrict__ Qm, const __half* __restrict__ KVm,
    __half* __restrict__ Oh, float scale)
{
    extern __shared__ char sh[];
    const int h = blockIdx.y;
    const int bm = blockIdx.x * 128;
    const int tid = threadIdx.x;
    const int lane = tid & 31, warp = tid >> 5;
    const int g = lane >> 2, t4 = lane & 3;
    const int wm = (warp & 3) * 32, wn = (warp >> 2) * 32;
    const int wN = warp >> 2;

    uint32_t sbase;
    asm("{ .reg .u64 t; cvta.to.shared.u64 t, %1; cvt.u32.u64 %0, t; }"
        : "=r"(sbase) : "l"(sh));
    float* redM = (float*)(sh + FK_RED);
    float* redS = redM + 512;

    const __half* Qg = Qm + (size_t)bm * 4096 + h * 128;
    const __half* Kg = KVm + (size_t)(h >> 2) * 128;
    const __half* Vg = KVm + 1024 + (size_t)(h >> 2) * 128;

#pragma unroll
    for (int j = 0; j < 4; j++) {
        int idx = tid + j * 512;
        int r = idx >> 4, c = idx & 15;
        CP16(sbase + (uint32_t)(r * 272 + c * 16), Qg + (size_t)r * 4096 + c * 8);
    }
    CP_COMMIT();

    auto cpK = [&](int t) {
        uint32_t dst = sbase + FK_K + (uint32_t)(t & 1) * 34816u;
        const __half* src = Kg + (size_t)t * 128 * 2048;
#pragma unroll
        for (int j = 0; j < 4; j++) {
            int idx = tid + j * 512;
            int r = idx >> 4, c = idx & 15;
            CP16(dst + (uint32_t)(r * 272 + c * 16), src + (size_t)r * 2048 + c * 8);
        }
        CP_COMMIT();
    };
    auto cpV = [&](int t) {
        uint32_t dst = sbase + FK_V;
        const __half* src = Vg + (size_t)t * 128 * 2048;
#pragma unroll
        for (int j = 0; j < 4; j++) {
            int idx = tid + j * 512;
            int r = idx >> 4, c = idx & 15;
            CP16(dst + (uint32_t)(r * 272 + c * 16), src + (size_t)r * 2048 + c * 8);
        }
        CP_COMMIT();
    };
    cpK(0);
    cpV(0);

    const int lr = (lane & 7) + ((lane >> 3) & 1) * 8;
    const int lk = lane >> 4;
    uint32_t qAddr[2], pAddr[2], kAddr[2], vAddr[2];
#pragma unroll
    for (int mi = 0; mi < 2; mi++) {
        qAddr[mi] = sbase + (uint32_t)((wm + mi * 16 + lr) * 272 + lk * 16);
        pAddr[mi] = sbase + FK_P + (uint32_t)((wm + mi * 16 + lr) * 272 + lk * 16);
    }
#pragma unroll
    for (int nb = 0; nb < 2; nb++) {
        kAddr[nb] = sbase + FK_K + (uint32_t)((wn + nb * 16 + lr) * 272 + lk * 16);
        vAddr[nb] = sbase + FK_V +
                    (uint32_t)(((lane & 7) + lk * 8) * 272 +
                               ((wn >> 3) + nb * 2 + ((lane >> 3) & 1)) * 16);
    }

    float accO[2][4][4];
#pragma unroll
    for (int i = 0; i < 2; i++)
#pragma unroll
        for (int j = 0; j < 4; j++)
#pragma unroll
            for (int l = 0; l < 4; l++) accO[i][j][l] = 0.f;
    float mrow[2][2] = {{-1e30f, -1e30f}, {-1e30f, -1e30f}};
    float lsum[2][2] = {{0.f, 0.f}, {0.f, 0.f}};

    for (int t = 0; t < 16; t++) {
        asm volatile("cp.async.wait_group 1;" ::: "memory");
        __syncthreads();

        float accS[2][4][4];
#pragma unroll
        for (int i = 0; i < 2; i++)
#pragma unroll
            for (int j = 0; j < 4; j++)
#pragma unroll
                for (int l = 0; l < 4; l++) accS[i][j][l] = 0.f;
        const uint32_t kst = (uint32_t)(t & 1) * 34816u;
#pragma unroll
        for (int kk = 0; kk < 8; kk++) {
            uint32_t QA[2][4], KB[4][2];
#pragma unroll
            for (int mi = 0; mi < 2; mi++)
                LDSM4(QA[mi][0], QA[mi][1], QA[mi][2], QA[mi][3], qAddr[mi] + kk * 32);
#pragma unroll
            for (int nb = 0; nb < 2; nb++) {
                uint32_t q0, q1, q2, q3;
                LDSM4(q0, q1, q2, q3, kAddr[nb] + kst + kk * 32);
                KB[2 * nb][0] = q0; KB[2 * nb][1] = q2;
                KB[2 * nb + 1][0] = q1; KB[2 * nb + 1][1] = q3;
            }
#pragma unroll
            for (int mi = 0; mi < 2; mi++)
#pragma unroll
                for (int ni = 0; ni < 4; ni++)
                    MMAH16816(accS[mi][ni], QA[mi][0], QA[mi][1], QA[mi][2], QA[mi][3],
                              KB[ni][0], KB[ni][1]);
        }
        if (t < 15) cpK(t + 1);

        float tm[2][2] = {{-1e30f, -1e30f}, {-1e30f, -1e30f}};
#pragma unroll
        for (int mi = 0; mi < 2; mi++)
#pragma unroll
            for (int ni = 0; ni < 4; ni++) {
                accS[mi][ni][0] *= scale; accS[mi][ni][1] *= scale;
                accS[mi][ni][2] *= scale; accS[mi][ni][3] *= scale;
                tm[mi][0] = fmaxf(tm[mi][0], fmaxf(accS[mi][ni][0], accS[mi][ni][1]));
                tm[mi][1] = fmaxf(tm[mi][1], fmaxf(accS[mi][ni][2], accS[mi][ni][3]));
            }
#pragma unroll
        for (int mi = 0; mi < 2; mi++)
#pragma unroll
            for (int hh = 0; hh < 2; hh++) {
                tm[mi][hh] = fmaxf(tm[mi][hh], __shfl_xor_sync(0xffffffffu, tm[mi][hh], 1));
                tm[mi][hh] = fmaxf(tm[mi][hh], __shfl_xor_sync(0xffffffffu, tm[mi][hh], 2));
            }
        if (t4 == 0)
#pragma unroll
            for (int mi = 0; mi < 2; mi++)
#pragma unroll
                for (int hh = 0; hh < 2; hh++)
                    redM[wN * 128 + wm + mi * 16 + g + hh * 8] = tm[mi][hh];
        __syncthreads();

        float Mn[2][2], al[2][2];
#pragma unroll
        for (int mi = 0; mi < 2; mi++)
#pragma unroll
            for (int hh = 0; hh < 2; hh++) {
                int row = wm + mi * 16 + g + hh * 8;
                float m = fmaxf(fmaxf(redM[row], redM[128 + row]),
                                fmaxf(redM[256 + row], redM[384 + row]));
                Mn[mi][hh] = fmaxf(mrow[mi][hh], m);
                al[mi][hh] = __expf(mrow[mi][hh] - Mn[mi][hh]);
                mrow[mi][hh] = Mn[mi][hh];
            }

        float rs[2][2] = {{0.f, 0.f}, {0.f, 0.f}};
#pragma unroll
        for (int mi = 0; mi < 2; mi++)
#pragma unroll
            for (int ni = 0; ni < 4; ni++) {
                float p0 = __expf(accS[mi][ni][0] - Mn[mi][0]);
                float p1 = __expf(accS[mi][ni][1] - Mn[mi][0]);
                float p2 = __expf(accS[mi][ni][2] - Mn[mi][1]);
                float p3 = __expf(accS[mi][ni][3] - Mn[mi][1]);
                rs[mi][0] += p0 + p1;
                rs[mi][1] += p2 + p3;
                __half2 hA = __floats2half2_rn(p0, p1);
                __half2 hB = __floats2half2_rn(p2, p3);
                uint32_t a0 = sbase + FK_P +
                              (uint32_t)((wm + mi * 16 + g) * 272 + (wn + ni * 8 + 2 * t4) * 2);
                STS32(a0, *(uint32_t*)&hA);
                STS32(a0 + 8 * 272, *(uint32_t*)&hB);
            }
#pragma unroll
        for (int mi = 0; mi < 2; mi++)
#pragma unroll
            for (int hh = 0; hh < 2; hh++) {
                rs[mi][hh] += __shfl_xor_sync(0xffffffffu, rs[mi][hh], 1);
                rs[mi][hh] += __shfl_xor_sync(0xffffffffu, rs[mi][hh], 2);
            }
        if (t4 == 0)
#pragma unroll
            for (int mi = 0; mi < 2; mi++)
#pragma unroll
                for (int hh = 0; hh < 2; hh++)
                    redS[wN * 128 + wm + mi * 16 + g + hh * 8] = rs[mi][hh];
        if (t < 15) asm volatile("cp.async.wait_group 1;" ::: "memory");
        else        asm volatile("cp.async.wait_group 0;" ::: "memory");
        __syncthreads();

#pragma unroll
        for (int mi = 0; mi < 2; mi++)
#pragma unroll
            for (int hh = 0; hh < 2; hh++) {
                int row = wm + mi * 16 + g + hh * 8;
                float rsum = redS[row] + redS[128 + row] + redS[256 + row] + redS[384 + row];
                lsum[mi][hh] = lsum[mi][hh] * al[mi][hh] + rsum;
            }
#pragma unroll
        for (int mi = 0; mi < 2; mi++)
#pragma unroll
            for (int ni = 0; ni < 4; ni++) {
                accO[mi][ni][0] *= al[mi][0]; accO[mi][ni][1] *= al[mi][0];
                accO[mi][ni][2] *= al[mi][1]; accO[mi][ni][3] *= al[mi][1];
            }

#pragma unroll
        for (int kk = 0; kk < 8; kk++) {
            uint32_t PA[2][4], VB[4][2];
#pragma unroll
            for (int mi = 0; mi < 2; mi++)
                LDSM4(PA[mi][0], PA[mi][1], PA[mi][2], PA[mi][3], pAddr[mi] + kk * 32);
#pragma unroll
            for (int nb = 0; nb < 2; nb++) {
                uint32_t q0, q1, q2, q3;
                LDSM4T(q0, q1, q2, q3, vAddr[nb] + kk * (16 * 272));
                VB[2 * nb][0] = q0; VB[2 * nb][1] = q2;
                VB[2 * nb + 1][0] = q1; VB[2 * nb + 1][1] = q3;
            }
#pragma unroll
            for (int mi = 0; mi < 2; mi++)
#pragma unroll
                for (int ni = 0; ni < 4; ni++)
                    MMAH16816(accO[mi][ni], PA[mi][0], PA[mi][1], PA[mi][2], PA[mi][3],
                              VB[ni][0], VB[ni][1]);
        }
        __syncthreads();
        if (t < 15) cpV(t + 1);
    }

    float inv[2][2];
#pragma unroll
    for (int mi = 0; mi < 2; mi++)
#pragma unroll
        for (int hh = 0; hh < 2; hh++) inv[mi][hh] = 1.0f / lsum[mi][hh];
#pragma unroll
    for (int mi = 0; mi < 2; mi++) {
        int rowg = bm + wm + mi * 16 + g;
#pragma unroll
        for (int ni = 0; ni < 4; ni++) {
            int colg = h * 128 + wn + ni * 8 + 2 * t4;
            *(__half2*)(Oh + (size_t)rowg * 4096 + colg) =
                __floats2half2_rn(accO[mi][ni][0] * inv[mi][0], accO[mi][ni][1] * inv[mi][0]);
            *(__half2*)(Oh + (size_t)(rowg + 8) * 4096 + colg) =
                __floats2half2_rn(accO[mi][ni][2] * inv[mi][1], accO[mi][ni][3] * inv[mi][1]);
        }
    }
}

extern "C" void kernel_launch(void* const* d_in, const int* in_sizes, int n_in,
                              void* d_out, int out_size) {
    const float* x  = (const float*)d_in[0];
    const float* fc = (const float*)d_in[1];
    const float* fs = (const float*)d_in[2];
    const float* wq = (const float*)d_in[3];
    const float* wk = (const float*)d_in[4];
    const float* wv = (const float*)d_in[5];
    const float* wo = (const float*)d_in[6];
    float* out = (float*)d_out;

    __half *xh, *wqh, *wql, *wkvh, *wkvl, *woh, *wol, *qh, *kvh, *ohh;
    cudaGetSymbolAddress((void**)&xh,   g_xh);
    cudaGetSymbolAddress((void**)&wqh,  g_wqh);  cudaGetSymbolAddress((void**)&wql,  g_wql);
    cudaGetSymbolAddress((void**)&wkvh, g_wkvh); cudaGetSymbolAddress((void**)&wkvl, g_wkvl);
    cudaGetSymbolAddress((void**)&woh,  g_woh);  cudaGetSymbolAddress((void**)&wol,  g_wol);
    cudaGetSymbolAddress((void**)&qh,   g_qh);
    cudaGetSymbolAddress((void**)&kvh,  g_kvh);
    cudaGetSymbolAddress((void**)&ohh,  g_ohh);

    const int SMW = 2 * W_STG;  // 172032
    cudaFuncSetAttribute(gemm_pc<true >, cudaFuncAttributeMaxDynamicSharedMemorySize, SMW);
    cudaFuncSetAttribute(gemm_pc<false>, cudaFuncAttributeMaxDynamicSharedMemorySize, SMW);
    cudaFuncSetAttribute(flash_k, cudaFuncAttributeMaxDynamicSharedMemorySize, FK_SM);

    const float scale = 0.08838834764831845f;  // 1/sqrt(128)

    // prep: fp16 planes
    cvt_x<<<8192, 256>>>(x, xh, SEQ * 4096 / 4);
    splitw<<<16384, 256>>>(wq, 1024, wqh, wql, 4096, 0);
    splitw<<< 4096, 256>>>(wk,  256, wkvh, wkvl, 2048, 0);
    splitw<<< 4096, 256>>>(wv,  256, wkvh, wkvl, 2048, 1024);
    splitw<<<16384, 256>>>(wo, 1024, woh, wol, 4096, 0);

    // projections
    gemm_pc<true ><<<dim3(16, 16), 256, SMW>>>(xh, 4096, wqh, wql, 4096, qh, 4096, 4096, fc, fs);
    gemm_pc<true ><<<dim3( 8, 16), 256, SMW>>>(xh, 4096, wkvh, wkvl, 2048, kvh, 2048, 1024, fc, fs);
    // attention
    flash_k<<<dim3(16, NHEADS), 512, FK_SM>>>(qh, kvh, ohh, scale);
    // output projection
    gemm_pc<false><<<dim3(16, 16), 256, SMW>>>(ohh, 4096, woh, wol, 4096, out, 4096, 0, nullptr, nullptr);
}

// round 17
// speedup vs baseline: 1.0528x; 1.0528x over previous
#include <cuda_runtime.h>
#include <cuda_fp16.h>
#include <cstdint>
#include <cstddef>

#define SEQ 2048
#define NHEADS 32

// ---------------- device scratch (fp16 planes) ----------------
__device__ __half g_xh[SEQ * 4096];
__device__ __half g_wqh[4096 * 4096], g_wql[4096 * 4096];
__device__ __half g_wkvh[4096 * 2048], g_wkvl[4096 * 2048];
__device__ __half g_woh[4096 * 4096], g_wol[4096 * 4096];
__device__ __half g_qh[SEQ * 4096];
__device__ __half g_kvh[SEQ * 2048];
__device__ __half g_ohh[SEQ * 4096];

#define MMAH16816(C, A0, A1, A2, A3, B0, B1)                                        \
    asm volatile(                                                                   \
        "mma.sync.aligned.m16n8k16.row.col.f32.f16.f16.f32 "                        \
        "{%0,%1,%2,%3},{%4,%5,%6,%7},{%8,%9},{%0,%1,%2,%3};"                        \
        : "+f"((C)[0]), "+f"((C)[1]), "+f"((C)[2]), "+f"((C)[3])                    \
        : "r"(A0), "r"(A1), "r"(A2), "r"(A3), "r"(B0), "r"(B1))
#define LDSM4(R0, R1, R2, R3, ADDR)                                                 \
    asm volatile("ldmatrix.sync.aligned.m8n8.x4.shared.b16 {%0,%1,%2,%3},[%4];"     \
                 : "=r"(R0), "=r"(R1), "=r"(R2), "=r"(R3) : "r"(ADDR))
#define LDSM4T(R0, R1, R2, R3, ADDR)                                                \
    asm volatile("ldmatrix.sync.aligned.m8n8.x4.trans.shared.b16 {%0,%1,%2,%3},[%4];" \
                 : "=r"(R0), "=r"(R1), "=r"(R2), "=r"(R3) : "r"(ADDR))
#define STS32(ADDR, V0) asm volatile("st.shared.b32 [%0],%1;" :: "r"(ADDR), "r"(V0))
#define CP16(saddr, gptr)                                                           \
    asm volatile("cp.async.cg.shared.global [%0], [%1], 16;" :: "r"(saddr), "l"(gptr))
#define CP_COMMIT() asm volatile("cp.async.commit_group;" ::: "memory")

// ---------------- prep kernels (one-time conversion) ----------------
__global__ void cvt_x(const float* __restrict__ in, __half* __restrict__ out, int n4) {
    int i = blockIdx.x * blockDim.x + threadIdx.x;
    if (i >= n4) return;
    float4 f = ((const float4*)in)[i];
    __half2 a = __floats2half2_rn(f.x, f.y);
    __half2 b = __floats2half2_rn(f.z, f.w);
    __half2* o = (__half2*)(out + (size_t)i * 4);
    o[0] = a; o[1] = b;
}

// w fp32 [4096][N] -> fp16 hi/lo planes [4096][ldo] at column offset co
__global__ void splitw(const float* __restrict__ w, int N4,
                       __half* __restrict__ wh, __half* __restrict__ wl,
                       int ldo, int co) {
    int i = blockIdx.x * blockDim.x + threadIdx.x;
    if (i >= 4096 * N4) return;
    int row = i / N4, c4 = i - row * N4;
    float4 f = ((const float4*)w)[i];
    __half2 h0 = __floats2half2_rn(f.x, f.y);
    __half2 h1 = __floats2half2_rn(f.z, f.w);
    float2 h0f = __half22float2(h0), h1f = __half22float2(h1);
    __half2 l0 = __floats2half2_rn(f.x - h0f.x, f.y - h0f.y);
    __half2 l1 = __floats2half2_rn(f.z - h1f.x, f.w - h1f.y);
    size_t off = (size_t)row * ldo + co + c4 * 4;
    ((__half2*)(wh + off))[0] = h0; ((__half2*)(wh + off))[1] = h1;
    ((__half2*)(wl + off))[0] = l0; ((__half2*)(wl + off))[1] = l1;
}

// ======================================================================
// preconverted fp16x2 GEMM: C[2048 x N] = A16 * (Bh + Bl).
// BM=128, BN=256, BK=64, 512 thr, warps 4(M)x4(N), warp tile 32x64.
// Pure cp.async mainloop, 2-deep, 64 stages. Two-wave B fragment reuse.
// smem/stage: A 0..18432 (pitch 144) | Bh 18432..52224 (pitch 528) | Bl ..86016
#define W_STG 86016
#define W_BH  18432u
#define W_BL  52224u

template <bool OUTH>
__global__ void __launch_bounds__(512, 1) gemm_pc(
    const __half* __restrict__ A, int lda,
    const __half* __restrict__ Bh, const __half* __restrict__ Bl, int ldb,
    void* __restrict__ Cout, int ldc, int ropeLim,
    const float* __restrict__ cosp, const float* __restrict__ sinp)
{
    extern __shared__ char sh[];
    const int tid = threadIdx.x;
    const int lane = tid & 31, warp = tid >> 5;
    const int g = lane >> 2, t4 = lane & 3;
    const int wm = (warp & 3) * 32, wn = (warp >> 2) * 64;
    const int bm = blockIdx.y * 128, bn = blockIdx.x * 256;

    uint32_t sbase;
    asm("{ .reg .u64 t; cvta.to.shared.u64 t, %1; cvt.u32.u64 %0, t; }"
        : "=r"(sbase) : "l"(sh));

    // cp.async coords: A 2 chunks/thread, B 4+4 chunks/thread
    uint32_t aDst[2];
    const __half* aSrc[2];
#pragma unroll
    for (int j = 0; j < 2; j++) {
        int idx = tid + j * 512;
        int r = idx >> 3, c = idx & 7;
        aDst[j] = (uint32_t)(r * 144 + c * 16);
        aSrc[j] = A + (size_t)(bm + r) * lda + c * 8;
    }
    uint32_t bDst[4];
    const __half* bSrcH[4];
    const __half* bSrcL[4];
#pragma unroll
    for (int j = 0; j < 4; j++) {
        int idx = tid + j * 512;
        int kr = idx >> 5, c = idx & 31;
        bDst[j] = W_BH + (uint32_t)(kr * 528 + c * 16);
        bSrcH[j] = Bh + (size_t)kr * ldb + bn + c * 8;
        bSrcL[j] = Bl + (size_t)kr * ldb + bn + c * 8;
    }

    auto loadStage = [&](int t) {
        const uint32_t so = sbase + (uint32_t)(t & 1) * W_STG;
        const size_t ko = (size_t)t * 64;
#pragma unroll
        for (int j = 0; j < 2; j++) CP16(so + aDst[j], aSrc[j] + ko);
#pragma unroll
        for (int j = 0; j < 4; j++) {
            CP16(so + bDst[j], bSrcH[j] + ko * ldb);
            CP16(so + bDst[j] + (W_BL - W_BH), bSrcL[j] + ko * ldb);
        }
        CP_COMMIT();
    };

    const int lr = (lane & 7) + ((lane >> 3) & 1) * 8;
    const int lk = lane >> 4;
    uint32_t aAddr[2], bAddr[4];
#pragma unroll
    for (int mi = 0; mi < 2; mi++)
        aAddr[mi] = sbase + (uint32_t)((wm + mi * 16 + lr) * 144 + lk * 16);
#pragma unroll
    for (int nb = 0; nb < 4; nb++) {
        int kk = (lane & 7) + lk * 8;
        int nc = (wn >> 3) + nb * 2 + ((lane >> 3) & 1);
        bAddr[nb] = sbase + W_BH + (uint32_t)(kk * 528 + nc * 16);
    }

    float acc[2][8][4];
#pragma unroll
    for (int i = 0; i < 2; i++)
#pragma unroll
        for (int j = 0; j < 8; j++)
#pragma unroll
            for (int l = 0; l < 4; l++) acc[i][j][l] = 0.f;

    const int nK = 64;  // K = 4096, BK = 64
    loadStage(0);

    for (int t = 0; t < nK; t++) {
        asm volatile("cp.async.wait_group 0;" ::: "memory");
        __syncthreads();
        if (t + 1 < nK) loadStage(t + 1);
        const uint32_t so = (uint32_t)(t & 1) * W_STG;
#pragma unroll
        for (int kb = 0; kb < 4; kb++) {
            uint32_t AH[2][4], BB[8][2];
#pragma unroll
            for (int mi = 0; mi < 2; mi++)
                LDSM4(AH[mi][0], AH[mi][1], AH[mi][2], AH[mi][3],
                      aAddr[mi] + so + kb * 32);
            // wave 1: B-lo fragments -> hl products
#pragma unroll
            for (int nb = 0; nb < 4; nb++) {
                uint32_t q0, q1, q2, q3;
                uint32_t bd = bAddr[nb] + so + kb * (16 * 528);
                LDSM4T(q0, q1, q2, q3, bd + (W_BL - W_BH));
                BB[2 * nb][0] = q0; BB[2 * nb][1] = q2;
                BB[2 * nb + 1][0] = q1; BB[2 * nb + 1][1] = q3;
            }
#pragma unroll
            for (int mi = 0; mi < 2; mi++)
#pragma unroll
                for (int ni = 0; ni < 8; ni++)
                    MMAH16816(acc[mi][ni], AH[mi][0], AH[mi][1], AH[mi][2], AH[mi][3],
                              BB[ni][0], BB[ni][1]);
            // wave 2: B-hi fragments (reuse regs) -> hh products
#pragma unroll
            for (int nb = 0; nb < 4; nb++) {
                uint32_t q0, q1, q2, q3;
                uint32_t bd = bAddr[nb] + so + kb * (16 * 528);
                LDSM4T(q0, q1, q2, q3, bd);
                BB[2 * nb][0] = q0; BB[2 * nb][1] = q2;
                BB[2 * nb + 1][0] = q1; BB[2 * nb + 1][1] = q3;
            }
#pragma unroll
            for (int mi = 0; mi < 2; mi++)
#pragma unroll
                for (int ni = 0; ni < 8; ni++)
                    MMAH16816(acc[mi][ni], AH[mi][0], AH[mi][1], AH[mi][2], AH[mi][3],
                              BB[ni][0], BB[ni][1]);
        }
    }

#pragma unroll
    for (int mi = 0; mi < 2; mi++) {
        int rowg = bm + wm + mi * 16 + g;
#pragma unroll
        for (int ni = 0; ni < 8; ni++) {
            int colg = bn + wn + ni * 8 + 2 * t4;
            float c0 = acc[mi][ni][0], c1 = acc[mi][ni][1];
            float c2 = acc[mi][ni][2], c3 = acc[mi][ni][3];
            if (colg < ropeLim) {
                int i = (colg & 127) >> 1;
                float cs = cosp[rowg * 64 + i], sn = sinp[rowg * 64 + i];
                float cs2 = cosp[(rowg + 8) * 64 + i], sn2 = sinp[(rowg + 8) * 64 + i];
                float o0 = c0 * cs - c1 * sn, o1 = c0 * sn + c1 * cs;
                float o2 = c2 * cs2 - c3 * sn2, o3 = c2 * sn2 + c3 * cs2;
                c0 = o0; c1 = o1; c2 = o2; c3 = o3;
            }
            if (OUTH) {
                __half* Ch = (__half*)Cout;
                *(__half2*)(Ch + (size_t)rowg * ldc + colg) = __floats2half2_rn(c0, c1);
                *(__half2*)(Ch + (size_t)(rowg + 8) * ldc + colg) = __floats2half2_rn(c2, c3);
            } else {
                float* Cf = (float*)Cout;
                *(float2*)(Cf + (size_t)rowg * ldc + colg) = make_float2(c0, c1);
                *(float2*)(Cf + (size_t)(rowg + 8) * ldc + colg) = make_float2(c2, c3);
            }
        }
    }
}

// ======== flash attention (K/V from merged [2048][2048] buffer; O -> fp16) ====
#define FK_K   34816u
#define FK_V   104448u
#define FK_P   139264u
#define FK_RED 174080u
#define FK_SM  178176

__global__ void __launch_bounds__(512, 1) flash_k(
    const __half* __restrict__ Qm, const __half* __restrict__ KVm,
    __half* __restrict__ Oh, float scale)
{
    extern __shared__ char sh[];
    const int h = blockIdx.y;
    const int bm = blockIdx.x * 128;
    const int tid = threadIdx.x;
    const int lane = tid & 31, warp = tid >> 5;
    const int g = lane >> 2, t4 = lane & 3;
    const int wm = (warp & 3) * 32, wn = (warp >> 2) * 32;
    const int wN = warp >> 2;

    uint32_t sbase;
    asm("{ .reg .u64 t; cvta.to.shared.u64 t, %1; cvt.u32.u64 %0, t; }"
        : "=r"(sbase) : "l"(sh));
    float* redM = (float*)(sh + FK_RED);
    float* redS = redM + 512;

    const __half* Qg = Qm + (size_t)bm * 4096 + h * 128;
    const __half* Kg = KVm + (size_t)(h >> 2) * 128;
    const __half* Vg = KVm + 1024 + (size_t)(h >> 2) * 128;

#pragma unroll
    for (int j = 0; j < 4; j++) {
        int idx = tid + j * 512;
        int r = idx >> 4, c = idx & 15;
        CP16(sbase + (uint32_t)(r * 272 + c * 16), Qg + (size_t)r * 4096 + c * 8);
    }
    CP_COMMIT();

    auto cpK = [&](int t) {
        uint32_t dst = sbase + FK_K + (uint32_t)(t & 1) * 34816u;
        const __half* src = Kg + (size_t)t * 128 * 2048;
#pragma unroll
        for (int j = 0; j < 4; j++) {
            int idx = tid + j * 512;
            int r = idx >> 4, c = idx & 15;
            CP16(dst + (uint32_t)(r * 272 + c * 16), src + (size_t)r * 2048 + c * 8);
        }
        CP_COMMIT();
    };
    auto cpV = [&](int t) {
        uint32_t dst = sbase + FK_V;
        const __half* src = Vg + (size_t)t * 128 * 2048;
#pragma unroll
        for (int j = 0; j < 4; j++) {
            int idx = tid + j * 512;
            int r = idx >> 4, c = idx & 15;
            CP16(dst + (uint32_t)(r * 272 + c * 16), src + (size_t)r * 2048 + c * 8);
        }
        CP_COMMIT();
    };
    cpK(0);
    cpV(0);

    const int lr = (lane & 7) + ((lane >> 3) & 1) * 8;
    const int lk = lane >> 4;
    uint32_t qAddr[2], pAddr[2], kAddr[2], vAddr[2];
#pragma unroll
    for (int mi = 0; mi < 2; mi++) {
        qAddr[mi] = sbase + (uint32_t)((wm + mi * 16 + lr) * 272 + lk * 16);
        pAddr[mi] = sbase + FK_P + (uint32_t)((wm + mi * 16 + lr) * 272 + lk * 16);
    }
#pragma unroll
    for (int nb = 0; nb < 2; nb++) {
        kAddr[nb] = sbase + FK_K + (uint32_t)((wn + nb * 16 + lr) * 272 + lk * 16);
        vAddr[nb] = sbase + FK_V +
                    (uint32_t)(((lane & 7) + lk * 8) * 272 +
                               ((wn >> 3) + nb * 2 + ((lane >> 3) & 1)) * 16);
    }

    float accO[2][4][4];
#pragma unroll
    for (int i = 0; i < 2; i++)
#pragma unroll
        for (int j = 0; j < 4; j++)
#pragma unroll
            for (int l = 0; l < 4; l++) accO[i][j][l] = 0.f;
    float mrow[2][2] = {{-1e30f, -1e30f}, {-1e30f, -1e30f}};
    float lsum[2][2] = {{0.f, 0.f}, {0.f, 0.f}};

    for (int t = 0; t < 16; t++) {
        asm volatile("cp.async.wait_group 1;" ::: "memory");
        __syncthreads();

        float accS[2][4][4];
#pragma unroll
        for (int i = 0; i < 2; i++)
#pragma unroll
            for (int j = 0; j < 4; j++)
#pragma unroll
                for (int l = 0; l < 4; l++) accS[i][j][l] = 0.f;
        const uint32_t kst = (uint32_t)(t & 1) * 34816u;
#pragma unroll
        for (int kk = 0; kk < 8; kk++) {
            uint32_t QA[2][4], KB[4][2];
#pragma unroll
            for (int mi = 0; mi < 2; mi++)
                LDSM4(QA[mi][0], QA[mi][1], QA[mi][2], QA[mi][3], qAddr[mi] + kk * 32);
#pragma unroll
            for (int nb = 0; nb < 2; nb++) {
                uint32_t q0, q1, q2, q3;
                LDSM4(q0, q1, q2, q3, kAddr[nb] + kst + kk * 32);
                KB[2 * nb][0] = q0; KB[2 * nb][1] = q2;
                KB[2 * nb + 1][0] = q1; KB[2 * nb + 1][1] = q3;
            }
#pragma unroll
            for (int mi = 0; mi < 2; mi++)
#pragma unroll
                for (int ni = 0; ni < 4; ni++)
                    MMAH16816(accS[mi][ni], QA[mi][0], QA[mi][1], QA[mi][2], QA[mi][3],
                              KB[ni][0], KB[ni][1]);
        }
        if (t < 15) cpK(t + 1);

        float tm[2][2] = {{-1e30f, -1e30f}, {-1e30f, -1e30f}};
#pragma unroll
        for (int mi = 0; mi < 2; mi++)
#pragma unroll
            for (int ni = 0; ni < 4; ni++) {
                accS[mi][ni][0] *= scale; accS[mi][ni][1] *= scale;
                accS[mi][ni][2] *= scale; accS[mi][ni][3] *= scale;
                tm[mi][0] = fmaxf(tm[mi][0], fmaxf(accS[mi][ni][0], accS[mi][ni][1]));
                tm[mi][1] = fmaxf(tm[mi][1], fmaxf(accS[mi][ni][2], accS[mi][ni][3]));
            }
#pragma unroll
        for (int mi = 0; mi < 2; mi++)
#pragma unroll
            for (int hh = 0; hh < 2; hh++) {
                tm[mi][hh] = fmaxf(tm[mi][hh], __shfl_xor_sync(0xffffffffu, tm[mi][hh], 1));
                tm[mi][hh] = fmaxf(tm[mi][hh], __shfl_xor_sync(0xffffffffu, tm[mi][hh], 2));
            }
        if (t4 == 0)
#pragma unroll
            for (int mi = 0; mi < 2; mi++)
#pragma unroll
                for (int hh = 0; hh < 2; hh++)
                    redM[wN * 128 + wm + mi * 16 + g + hh * 8] = tm[mi][hh];
        __syncthreads();

        float Mn[2][2], al[2][2];
#pragma unroll
        for (int mi = 0; mi < 2; mi++)
#pragma unroll
            for (int hh = 0; hh < 2; hh++) {
                int row = wm + mi * 16 + g + hh * 8;
                float m = fmaxf(fmaxf(redM[row], redM[128 + row]),
                                fmaxf(redM[256 + row], redM[384 + row]));
                Mn[mi][hh] = fmaxf(mrow[mi][hh], m);
                al[mi][hh] = __expf(mrow[mi][hh] - Mn[mi][hh]);
                mrow[mi][hh] = Mn[mi][hh];
            }

        float rs[2][2] = {{0.f, 0.f}, {0.f, 0.f}};
#pragma unroll
        for (int mi = 0; mi < 2; mi++)
#pragma unroll
            for (int ni = 0; ni < 4; ni++) {
                float p0 = __expf(accS[mi][ni][0] - Mn[mi][0]);
                float p1 = __expf(accS[mi][ni][1] - Mn[mi][0]);
                float p2 = __expf(accS[mi][ni][2] - Mn[mi][1]);
                float p3 = __expf(accS[mi][ni][3] - Mn[mi][1]);
                rs[mi][0] += p0 + p1;
                rs[mi][1] += p2 + p3;
                __half2 hA = __floats2half2_rn(p0, p1);
                __half2 hB = __floats2half2_rn(p2, p3);
                uint32_t a0 = sbase + FK_P +
                              (uint32_t)((wm + mi * 16 + g) * 272 + (wn + ni * 8 + 2 * t4) * 2);
                STS32(a0, *(uint32_t*)&hA);
                STS32(a0 + 8 * 272, *(uint32_t*)&hB);
            }
#pragma unroll
        for (int mi = 0; mi < 2; mi++)
#pragma unroll
            for (int hh = 0; hh < 2; hh++) {
                rs[mi][hh] += __shfl_xor_sync(0xffffffffu, rs[mi][hh], 1);
                rs[mi][hh] += __shfl_xor_sync(0xffffffffu, rs[mi][hh], 2);
            }
        if (t4 == 0)
#pragma unroll
            for (int mi = 0; mi < 2; mi++)
#pragma unroll
                for (int hh = 0; hh < 2; hh++)
                    redS[wN * 128 + wm + mi * 16 + g + hh * 8] = rs[mi][hh];
        if (t < 15) asm volatile("cp.async.wait_group 1;" ::: "memory");
        else        asm volatile("cp.async.wait_group 0;" ::: "memory");
        __syncthreads();

#pragma unroll
        for (int mi = 0; mi < 2; mi++)
#pragma unroll
            for (int hh = 0; hh < 2; hh++) {
                int row = wm + mi * 16 + g + hh * 8;
                float rsum = redS[row] + redS[128 + row] + redS[256 + row] + redS[384 + row];
                lsum[mi][hh] = lsum[mi][hh] * al[mi][hh] + rsum;
            }
#pragma unroll
        for (int mi = 0; mi < 2; mi++)
#pragma unroll
            for (int ni = 0; ni < 4; ni++) {
                accO[mi][ni][0] *= al[mi][0]; accO[mi][ni][1] *= al[mi][0];
                accO[mi][ni][2] *= al[mi][1]; accO[mi][ni][3] *= al[mi][1];
            }

#pragma unroll
        for (int kk = 0; kk < 8; kk++) {
            uint32_t PA[2][4], VB[4][2];
#pragma unroll
            for (int mi = 0; mi < 2; mi++)
                LDSM4(PA[mi][0], PA[mi][1], PA[mi][2], PA[mi][3], pAddr[mi] + kk * 32);
#pragma unroll
            for (int nb = 0; nb < 2; nb++) {
                uint32_t q0, q1, q2, q3;
                LDSM4T(q0, q1, q2, q3, vAddr[nb] + kk * (16 * 272));
                VB[2 * nb][0] = q0; VB[2 * nb][1] = q2;
                VB[2 * nb + 1][0] = q1; VB[2 * nb + 1][1] = q3;
            }
#pragma unroll
            for (int mi = 0; mi < 2; mi++)
#pragma unroll
                for (int ni = 0; ni < 4; ni++)
                    MMAH16816(accO[mi][ni], PA[mi][0], PA[mi][1], PA[mi][2], PA[mi][3],
                              VB[ni][0], VB[ni][1]);
        }
        __syncthreads();
        if (t < 15) cpV(t + 1);
    }

    float inv[2][2];
#pragma unroll
    for (int mi = 0; mi < 2; mi++)
#pragma unroll
        for (int hh = 0; hh < 2; hh++) inv[mi][hh] = 1.0f / lsum[mi][hh];
#pragma unroll
    for (int mi = 0; mi < 2; mi++) {
        int rowg = bm + wm + mi * 16 + g;
#pragma unroll
        for (int ni = 0; ni < 4; ni++) {
            int colg = h * 128 + wn + ni * 8 + 2 * t4;
            *(__half2*)(Oh + (size_t)rowg * 4096 + colg) =
                __floats2half2_rn(accO[mi][ni][0] * inv[mi][0], accO[mi][ni][1] * inv[mi][0]);
            *(__half2*)(Oh + (size_t)(rowg + 8) * 4096 + colg) =
                __floats2half2_rn(accO[mi][ni][2] * inv[mi][1], accO[mi][ni][3] * inv[mi][1]);
        }
    }
}

extern "C" void kernel_launch(void* const* d_in, const int* in_sizes, int n_in,
                              void* d_out, int out_size) {
    const float* x  = (const float*)d_in[0];
    const float* fc = (const float*)d_in[1];
    const float* fs = (const float*)d_in[2];
    const float* wq = (const float*)d_in[3];
    const float* wk = (const float*)d_in[4];
    const float* wv = (const float*)d_in[5];
    const float* wo = (const float*)d_in[6];
    float* out = (float*)d_out;

    __half *xh, *wqh, *wql, *wkvh, *wkvl, *woh, *wol, *qh, *kvh, *ohh;
    cudaGetSymbolAddress((void**)&xh,   g_xh);
    cudaGetSymbolAddress((void**)&wqh,  g_wqh);  cudaGetSymbolAddress((void**)&wql,  g_wql);
    cudaGetSymbolAddress((void**)&wkvh, g_wkvh); cudaGetSymbolAddress((void**)&wkvl, g_wkvl);
    cudaGetSymbolAddress((void**)&woh,  g_woh);  cudaGetSymbolAddress((void**)&wol,  g_wol);
    cudaGetSymbolAddress((void**)&qh,   g_qh);
    cudaGetSymbolAddress((void**)&kvh,  g_kvh);
    cudaGetSymbolAddress((void**)&ohh,  g_ohh);

    const int SMW = 2 * W_STG;  // 172032
    cudaFuncSetAttribute(gemm_pc<true >, cudaFuncAttributeMaxDynamicSharedMemorySize, SMW);
    cudaFuncSetAttribute(gemm_pc<false>, cudaFuncAttributeMaxDynamicSharedMemorySize, SMW);
    cudaFuncSetAttribute(flash_k, cudaFuncAttributeMaxDynamicSharedMemorySize, FK_SM);

    const float scale = 0.08838834764831845f;  // 1/sqrt(128)

    // prep: fp16 planes
    cvt_x<<<8192, 256>>>(x, xh, SEQ * 4096 / 4);
    splitw<<<16384, 256>>>(wq, 1024, wqh, wql, 4096, 0);
    splitw<<< 4096, 256>>>(wk,  256, wkvh, wkvl, 2048, 0);
    splitw<<< 4096, 256>>>(wv,  256, wkvh, wkvl, 2048, 1024);
    splitw<<<16384, 256>>>(wo, 1024, woh, wol, 4096, 0);

    // projections
    gemm_pc<true ><<<dim3(16, 16), 512, SMW>>>(xh, 4096, wqh, wql, 4096, qh, 4096, 4096, fc, fs);
    gemm_pc<true ><<<dim3( 8, 16), 512, SMW>>>(xh, 4096, wkvh, wkvl, 2048, kvh, 2048, 1024, fc, fs);
    // attention
    flash_k<<<dim3(16, NHEADS), 512, FK_SM>>>(qh, kvh, ohh, scale);
    // output projection
    gemm_pc<false><<<dim3(16, 16), 512, SMW>>>(ohh, 4096, woh, wol, 4096, out, 4096, 0, nullptr, nullptr);
}